// round 3
// baseline (speedup 1.0000x reference)
#include <cuda_runtime.h>
#include <cstdint>
#include <cstddef>

#define DH __host__ __device__

// ---------------- compile-time DCT constants ----------------
DH constexpr double tcos_core(double x) {
    double x2 = x * x, t = 1.0, s = 1.0;
    for (int i = 1; i <= 12; i++) { t *= -x2 / (double)((2 * i - 1) * (2 * i)); s += t; }
    return s;
}
DH constexpr double dctcosd(int f, int p) {
    int m = ((2 * p + 1) * f) % 128;
    double sg = 1.0;
    if (m > 64) m = 128 - m;
    if (m > 32) { sg = -1.0; m = 64 - m; }
    const double PI = 3.14159265358979323846264338327950288;
    return sg * tcos_core((double)m * PI / 64.0);
}
DH constexpr double rsqrt2c() {
    double g = 0.7;
    for (int i = 0; i < 50; i++) g = 0.5 * (g + 0.5 / g);
    return g;
}
DH constexpr float c1val(int v, int y) {  // vertical: fold c_v
    return (float)(dctcosd(v, y) * (v == 0 ? rsqrt2c() : 1.0));
}
DH constexpr float c2val(int u, int x) {  // horizontal: fold c_u and 2/32
    return (float)(dctcosd(u, x) * (u == 0 ? rsqrt2c() : 1.0) * (2.0 / 32.0));
}

// ---------------- stage 1: vertical DCT, one parity half per thread ----------------
// PAR=0: even v from s = lo+hi; PAR=1: odd v from d = lo-hi.
template <int PAR, int P, int V> struct S1V {
    static __device__ __forceinline__ void run(float val, float (&a)[16]) {
        constexpr float c = c1val(2 * V + PAR, P);
        a[V] = fmaf(val, c, a[V]);
        S1V<PAR, P, V + 1>::run(val, a);
    }
};
template <int PAR, int P> struct S1V<PAR, P, 16> {
    static __device__ __forceinline__ void run(float, float (&)[16]) {}
};
template <int PAR, int P> struct S1P {
    static __device__ __forceinline__ void run(const float* __restrict__ yc, int gcol,
                                               float (&a)[16]) {
        float lo = yc[P * 132 + gcol];
        float hi = yc[(31 - P) * 132 + gcol];
        float val = PAR ? (lo - hi) : (lo + hi);
        S1V<PAR, P, 0>::run(val, a);
        S1P<PAR, P + 1>::run(yc, gcol, a);
    }
};
template <int PAR> struct S1P<PAR, 16> {
    static __device__ __forceinline__ void run(const float* __restrict__, int, float (&)[16]) {}
};

// ---------------- stage 2: horizontal DCT, one u-parity half per thread ----------------
template <int UH, int P, int J> struct S2U {
    static __device__ __forceinline__ void run(float val, float (&a)[16]) {
        constexpr float c = c2val(2 * J + UH, P);
        a[J] = fmaf(val, c, a[J]);
        S2U<UH, P, J + 1>::run(val, a);
    }
};
template <int UH, int P> struct S2U<UH, P, 16> {
    static __device__ __forceinline__ void run(float, float (&)[16]) {}
};
template <int UH, int P> struct S2P {
    static __device__ __forceinline__ void run(const float* __restrict__ t, float (&a)[16]) {
        float lo = t[P], hi = t[31 - P];
        float val = UH ? (lo - hi) : (lo + hi);
        S2U<UH, P, 0>::run(val, a);
        S2P<UH, P + 1>::run(t, a);
    }
};
template <int UH> struct S2P<UH, 16> {
    static __device__ __forceinline__ void run(const float* __restrict__, float (&)[16]) {}
};

// ---------------- permutation derivation from the kernels input ----------------
__device__ int g_pos[1024];  // pos[v*32+u] = output channel index k

__device__ __forceinline__ unsigned long long lanemax_ull(unsigned long long k) {
    #pragma unroll
    for (int o = 16; o; o >>= 1) {
        unsigned long long other = __shfl_xor_sync(0xffffffffu, k, o);
        if (other > k) k = other;
    }
    return k;
}

__global__ void perm_kernel(const float* __restrict__ ker) {
    int k = blockIdx.x * 8 + (threadIdx.x >> 5);
    int f = threadIdx.x & 31;
    const float* K = ker + (size_t)k * 1024;
    float s = 0.f, t = 0.f;
    #pragma unroll
    for (int x = 0; x < 32; x++) {
        float c = cospif((float)((2 * x + 1) * f) * (1.0f / 64.0f));
        s = fmaf(K[x],      c, s);
        t = fmaf(K[x * 32], c, t);
    }
    unsigned long long ks = (((unsigned long long)__float_as_uint(fabsf(s))) << 32) | (unsigned)f;
    unsigned long long kt = (((unsigned long long)__float_as_uint(fabsf(t))) << 32) | (unsigned)f;
    ks = lanemax_ull(ks);
    kt = lanemax_ull(kt);
    if (f == 0) {
        g_pos[(int)(kt & 31u) * 32 + (int)(ks & 31u)] = k;
    }
}

// ---------------- main fused kernel ----------------
// Grid: (ng=4, m=16, b=32). CTA = 768 threads, one 32-row x 128-col strip (4 blocks).
// Dynamic SMEM: ycc[3*32*132] (YCbCr pixels, group-padded) + tmp[3*32*132] (stage-1 out).
static constexpr int HALF_FLOATS = 3 * 32 * 132;   // 12672
static constexpr int DYN_BYTES = 2 * HALF_FLOATS * 4;  // 101376 B

__global__ void __launch_bounds__(768, 2)
dct_main(const float* __restrict__ rgb, float* __restrict__ out) {
    extern __shared__ float smem_dyn[];
    float* ycc = smem_dyn;                 // [ch][row][col-padded]
    float* tmp = smem_dyn + HALF_FLOATS;   // [ch*32+v][col-padded]
    __shared__ int pos_s[1024];

    const int tid = threadIdx.x;
    const int ng = blockIdx.x;   // n-group (4 blocks each)
    const int m  = blockIdx.y;   // block row
    const int b  = blockIdx.z;   // batch

    for (int i = tid; i < 1024; i += 768) pos_s[i] = g_pos[i];

    // ---- stage 0: load tile once, RGB->YCbCr once, stage to SMEM ----
    const size_t plane = (size_t)512 * 512;
    const float* rbase = rgb + (size_t)b * 3 * plane + (size_t)(m * 32) * 512 + ng * 128;

    #pragma unroll 1
    for (int p = tid; p < 4096; p += 768) {
        int row = p >> 7, col = p & 127;
        const float* q = rbase + row * 512 + col;
        float rv = q[0], gv = q[plane], bv = q[2 * plane];
        float y0  = fmaf(0.299f, rv, fmaf(0.587f, gv, 0.114f * bv));
        float py  = fmaf(2.0f, y0, -1.0f);
        float pcb = (bv - y0) * 1.128f;
        float pcr = (rv - y0) * 1.426f;
        int go = row * 132 + (col >> 5) * 33 + (col & 31);
        ycc[go]            = py;
        ycc[32 * 132 + go] = pcb;
        ycc[64 * 132 + go] = pcr;
    }
    __syncthreads();

    // ---- stage 1: vertical butterfly DCT. thread = (ch, parity, col). ----
    {
        const int grp = tid >> 7;          // 0..5
        const int col = tid & 127;
        const int ch = grp >> 1, par = grp & 1;
        const int gcol = (col >> 5) * 33 + (col & 31);
        const float* yc = ycc + ch * 32 * 132;

        float acc[16];
        #pragma unroll
        for (int i = 0; i < 16; i++) acc[i] = 0.f;

        if (par == 0) S1P<0, 0>::run(yc, gcol, acc);
        else          S1P<1, 0>::run(yc, gcol, acc);

        float* tb = tmp + (ch * 32 + par) * 132 + gcol;
        #pragma unroll
        for (int vi = 0; vi < 16; vi++)
            tb[2 * vi * 132] = acc[vi];
    }
    __syncthreads();

    // ---- stage 2: horizontal butterfly DCT. thread = (c, v, nblk, uhalf). ----
    {
        const int cv = tid >> 3;            // 0..95
        const int c  = cv >> 5, v = cv & 31;
        const int nblk = (tid >> 1) & 3;
        const int uh = tid & 1;
        const float* t = tmp + cv * 132 + nblk * 33;

        float a2[16];
        #pragma unroll
        for (int i = 0; i < 16; i++) a2[i] = 0.f;

        if (uh == 0) S2P<0, 0>::run(t, a2);
        else         S2P<1, 0>::run(t, a2);

        const int n = ng * 4 + nblk;
        float* ob = out + (size_t)b * 3072 * 256 + (size_t)c * 1024 * 256 + m * 16 + n;
        const int* pv = pos_s + v * 32;
        #pragma unroll
        for (int j = 0; j < 16; j++) {
            ob[(size_t)pv[2 * j + uh] * 256] = a2[j];
        }
    }
}

// ---------------- launch ----------------
extern "C" void kernel_launch(void* const* d_in, const int* in_sizes, int n_in,
                              void* d_out, int out_size) {
    const float* rgb = (const float*)d_in[0];
    const float* ker = (const float*)d_in[1];
    float* out = (float*)d_out;

    perm_kernel<<<128, 256>>>(ker);

    cudaFuncSetAttribute(dct_main, cudaFuncAttributeMaxDynamicSharedMemorySize, DYN_BYTES);
    dct_main<<<dim3(4, 16, 32), 768, DYN_BYTES>>>(rgb, out);
}

// round 4
// speedup vs baseline: 1.4123x; 1.4123x over previous
#include <cuda_runtime.h>
#include <cstdint>
#include <cstddef>

#define DH __host__ __device__

// ---------------- compile-time DCT constants ----------------
DH constexpr double tcos_core(double x) {
    double x2 = x * x, t = 1.0, s = 1.0;
    for (int i = 1; i <= 12; i++) { t *= -x2 / (double)((2 * i - 1) * (2 * i)); s += t; }
    return s;
}
DH constexpr double dctcosd(int f, int p) {
    int m = ((2 * p + 1) * f) % 128;
    double sg = 1.0;
    if (m > 64) m = 128 - m;
    if (m > 32) { sg = -1.0; m = 64 - m; }
    const double PI = 3.14159265358979323846264338327950288;
    return sg * tcos_core((double)m * PI / 64.0);
}
DH constexpr double rsqrt2c() {
    double g = 0.7;
    for (int i = 0; i < 50; i++) g = 0.5 * (g + 0.5 / g);
    return g;
}
DH constexpr float c1val(int v, int y) {  // vertical: fold c_v
    return (float)(dctcosd(v, y) * (v == 0 ? rsqrt2c() : 1.0));
}
DH constexpr float c2val(int u, int x) {  // horizontal: fold c_u and 2/32
    return (float)(dctcosd(u, x) * (u == 0 ? rsqrt2c() : 1.0) * (2.0 / 32.0));
}

// ---------------- stage 1: vertical butterfly DCT, one parity per thread ----------------
// PAR=0: even v from s = lo+hi; PAR=1: odd v from d = lo-hi.
template <int PAR, int P, int V> struct S1V {
    static __device__ __forceinline__ void run(float vy, float vb, float vr,
                                               float (&a)[3][16]) {
        constexpr float c = c1val(2 * V + PAR, P);
        a[0][V] = fmaf(vy, c, a[0][V]);
        a[1][V] = fmaf(vb, c, a[1][V]);
        a[2][V] = fmaf(vr, c, a[2][V]);
        S1V<PAR, P, V + 1>::run(vy, vb, vr, a);
    }
};
template <int PAR, int P> struct S1V<PAR, P, 16> {
    static __device__ __forceinline__ void run(float, float, float, float (&)[3][16]) {}
};

__device__ __forceinline__ void ycbcr(float rv, float gv, float bv,
                                      float& py, float& pcb, float& pcr) {
    float y0 = fmaf(0.299f, rv, fmaf(0.587f, gv, 0.114f * bv));
    py  = fmaf(2.0f, y0, -1.0f);
    pcb = (bv - y0) * 1.128f;   // 2*0.564
    pcr = (rv - y0) * 1.426f;   // 2*0.713
}

template <int PAR, int P> struct S1P {
    static __device__ __forceinline__ void run(const float* __restrict__ r,
                                               const float* __restrict__ g,
                                               const float* __restrict__ b,
                                               float (&a)[3][16]) {
        constexpr int Q = 31 - P;
        float rl = r[P * 512], gl = g[P * 512], bl = b[P * 512];
        float rh = r[Q * 512], gh = g[Q * 512], bh = b[Q * 512];
        float pyl, pcbl, pcrl, pyh, pcbh, pcrh;
        ycbcr(rl, gl, bl, pyl, pcbl, pcrl);
        ycbcr(rh, gh, bh, pyh, pcbh, pcrh);
        float vy, vb, vr;
        if (PAR == 0) { vy = pyl + pyh; vb = pcbl + pcbh; vr = pcrl + pcrh; }
        else          { vy = pyl - pyh; vb = pcbl - pcbh; vr = pcrl - pcrh; }
        S1V<PAR, P, 0>::run(vy, vb, vr, a);
        S1P<PAR, P + 1>::run(r, g, b, a);
    }
};
template <int PAR> struct S1P<PAR, 16> {
    static __device__ __forceinline__ void run(const float*, const float*, const float*,
                                               float (&)[3][16]) {}
};

// ---------------- stage 2: horizontal butterfly DCT, one u-parity per thread ----------------
template <int UH, int P, int J> struct S2U {
    static __device__ __forceinline__ void run(float val, float (&a)[16]) {
        constexpr float c = c2val(2 * J + UH, P);
        a[J] = fmaf(val, c, a[J]);
        S2U<UH, P, J + 1>::run(val, a);
    }
};
template <int UH, int P> struct S2U<UH, P, 16> {
    static __device__ __forceinline__ void run(float, float (&)[16]) {}
};
template <int UH, int P> struct S2P {
    static __device__ __forceinline__ void run(const float* __restrict__ t, float (&a)[16]) {
        float lo = t[P], hi = t[31 - P];
        float val = UH ? (lo - hi) : (lo + hi);
        S2U<UH, P, 0>::run(val, a);
        S2P<UH, P + 1>::run(t, a);
    }
};
template <int UH> struct S2P<UH, 16> {
    static __device__ __forceinline__ void run(const float* __restrict__, float (&)[16]) {}
};

// ---------------- permutation derivation from the kernels input ----------------
__device__ int g_pos[1024];  // pos[v*32+u] = output channel index k

__device__ __forceinline__ unsigned long long lanemax_ull(unsigned long long k) {
    #pragma unroll
    for (int o = 16; o; o >>= 1) {
        unsigned long long other = __shfl_xor_sync(0xffffffffu, k, o);
        if (other > k) k = other;
    }
    return k;
}

__global__ void perm_kernel(const float* __restrict__ ker) {
    int k = blockIdx.x * 8 + (threadIdx.x >> 5);
    int f = threadIdx.x & 31;
    const float* K = ker + (size_t)k * 1024;
    float s = 0.f, t = 0.f;
    #pragma unroll
    for (int x = 0; x < 32; x++) {
        float c = cospif((float)((2 * x + 1) * f) * (1.0f / 64.0f));
        s = fmaf(K[x],      c, s);
        t = fmaf(K[x * 32], c, t);
    }
    unsigned long long ks = (((unsigned long long)__float_as_uint(fabsf(s))) << 32) | (unsigned)f;
    unsigned long long kt = (((unsigned long long)__float_as_uint(fabsf(t))) << 32) | (unsigned)f;
    ks = lanemax_ull(ks);
    kt = lanemax_ull(kt);
    if (f == 0) {
        g_pos[(int)(kt & 31u) * 32 + (int)(ks & 31u)] = k;
    }
}

// ---------------- main fused kernel ----------------
// Grid: (ng=2, m=16, b=32). CTA = 512 threads, one 32-row x 256-col strip (8 blocks).
// Stage 1: thread = (parity, col); all 3 channels, 48 accumulators.
// SMEM tmp layout: tmp[c][v][x] at (c*32+v)*264 + (x/32)*33 + (x%32).
static constexpr int TMP_FLOATS = 3 * 32 * 264;  // 25344 floats = 101376 B

__global__ void __launch_bounds__(512, 2)
dct_main(const float* __restrict__ rgb, float* __restrict__ out) {
    extern __shared__ float tmp[];
    __shared__ int pos_s[1024];

    const int tid = threadIdx.x;
    const int ng = blockIdx.x;   // n-group (8 blocks each)
    const int m  = blockIdx.y;   // block row
    const int b  = blockIdx.z;   // batch

    #pragma unroll
    for (int i = 0; i < 2; i++) pos_s[i * 512 + tid] = g_pos[i * 512 + tid];

    // ---- stage 1: vertical butterfly DCT of this thread's pixel column ----
    const size_t plane = (size_t)512 * 512;
    const int col = tid & 255;
    const int par = tid >> 8;
    const float* base = rgb + (size_t)b * 3 * plane + (size_t)(m * 32) * 512 + ng * 256 + col;

    float acc[3][16];
    #pragma unroll
    for (int c = 0; c < 3; c++)
        #pragma unroll
        for (int v = 0; v < 16; v++) acc[c][v] = 0.f;

    if (par == 0) S1P<0, 0>::run(base, base + plane, base + 2 * plane, acc);
    else          S1P<1, 0>::run(base, base + plane, base + 2 * plane, acc);

    const int go = (col >> 5) * 33 + (col & 31);
    #pragma unroll
    for (int c = 0; c < 3; c++)
        #pragma unroll
        for (int vi = 0; vi < 16; vi++)
            tmp[(c * 32 + 2 * vi + par) * 264 + go] = acc[c][vi];

    __syncthreads();

    // ---- stage 2: horizontal butterfly DCT. thread = (v, nblk, uh), loop c. ----
    // Warp lanes: fixed (v,uh), nblk varies over 8 -> each STG.32 covers 32B.
    const int uh = tid & 1;
    const int nblk = (tid >> 1) & 7;
    const int v = tid >> 4;              // 0..31
    const int n = ng * 8 + nblk;
    float* ob = out + (((size_t)b * 3072) * 16 + m) * 16 + n;
    const int* pv = pos_s + v * 32;

    #pragma unroll 1
    for (int c = 0; c < 3; c++) {
        float a2[16];
        #pragma unroll
        for (int j = 0; j < 16; j++) a2[j] = 0.f;

        const float* t = tmp + (c * 32 + v) * 264 + nblk * 33;
        if (uh == 0) S2P<0, 0>::run(t, a2);
        else         S2P<1, 0>::run(t, a2);

        float* obc = ob + (size_t)c * 1024 * 256;
        #pragma unroll
        for (int j = 0; j < 16; j++) {
            obc[(size_t)pv[2 * j + uh] * 256] = a2[j];  // bijective over outputs
        }
    }
}

// ---------------- launch ----------------
extern "C" void kernel_launch(void* const* d_in, const int* in_sizes, int n_in,
                              void* d_out, int out_size) {
    const float* rgb = (const float*)d_in[0];
    const float* ker = (const float*)d_in[1];
    float* out = (float*)d_out;

    perm_kernel<<<128, 256>>>(ker);

    cudaFuncSetAttribute(dct_main, cudaFuncAttributeMaxDynamicSharedMemorySize,
                         TMP_FLOATS * (int)sizeof(float));
    dct_main<<<dim3(2, 16, 32), 512, TMP_FLOATS * (int)sizeof(float)>>>(rgb, out);
}

// round 5
// speedup vs baseline: 1.5588x; 1.1037x over previous
#include <cuda_runtime.h>
#include <cstdint>
#include <cstddef>

#define DH __host__ __device__

// ---------------- compile-time DCT constants ----------------
DH constexpr double tcos_core(double x) {
    double x2 = x * x, t = 1.0, s = 1.0;
    for (int i = 1; i <= 12; i++) { t *= -x2 / (double)((2 * i - 1) * (2 * i)); s += t; }
    return s;
}
DH constexpr double dctcosd(int f, int p) {
    int m = ((2 * p + 1) * f) % 128;
    double sg = 1.0;
    if (m > 64) m = 128 - m;
    if (m > 32) { sg = -1.0; m = 64 - m; }
    const double PI = 3.14159265358979323846264338327950288;
    return sg * tcos_core((double)m * PI / 64.0);
}
DH constexpr double rsqrt2c() {
    double g = 0.7;
    for (int i = 0; i < 50; i++) g = 0.5 * (g + 0.5 / g);
    return g;
}
DH constexpr float c1val(int v, int y) {  // vertical: fold c_v
    return (float)(dctcosd(v, y) * (v == 0 ? rsqrt2c() : 1.0));
}
DH constexpr float c2val(int u, int x) {  // horizontal: fold c_u and 2/32
    return (float)(dctcosd(u, x) * (u == 0 ? rsqrt2c() : 1.0) * (2.0 / 32.0));
}

// ---------------- stage 1: vertical butterfly DCT, single plane, 32 accs ----------------
template <int P, int V> struct S1V {
    static __device__ __forceinline__ void run(float s, float d, float (&a)[32]) {
        a[2 * V]     = fmaf(s, c1val(2 * V,     P), a[2 * V]);
        a[2 * V + 1] = fmaf(d, c1val(2 * V + 1, P), a[2 * V + 1]);
        S1V<P, V + 1>::run(s, d, a);
    }
};
template <int P> struct S1V<P, 16> {
    static __device__ __forceinline__ void run(float, float, float (&)[32]) {}
};
template <int P> struct S1P {
    static __device__ __forceinline__ void run(const float* __restrict__ q, float (&a)[32]) {
        float lo = q[P * 512], hi = q[(31 - P) * 512];
        S1V<P, 0>::run(lo + hi, lo - hi, a);
        S1P<P + 1>::run(q, a);
    }
};
template <> struct S1P<16> {
    static __device__ __forceinline__ void run(const float* __restrict__, float (&)[32]) {}
};

// ---------------- stage 2: horizontal butterfly DCT, 32 accs ----------------
template <int P, int J> struct S2U {
    static __device__ __forceinline__ void run(float s, float d, float (&a)[32]) {
        a[2 * J]     = fmaf(s, c2val(2 * J,     P), a[2 * J]);
        a[2 * J + 1] = fmaf(d, c2val(2 * J + 1, P), a[2 * J + 1]);
        S2U<P, J + 1>::run(s, d, a);
    }
};
template <int P> struct S2U<P, 16> {
    static __device__ __forceinline__ void run(float, float, float (&)[32]) {}
};
template <int P> struct S2P {
    static __device__ __forceinline__ void run(const float* __restrict__ t, float (&a)[32]) {
        float lo = t[P], hi = t[31 - P];
        S2U<P, 0>::run(lo + hi, lo - hi, a);
        S2P<P + 1>::run(t, a);
    }
};
template <> struct S2P<16> {
    static __device__ __forceinline__ void run(const float* __restrict__, float (&)[32]) {}
};

// ---------------- permutation derivation from the kernels input ----------------
__device__ int g_pos[1024];  // pos[v*32+u] = output channel index k

__device__ __forceinline__ unsigned long long lanemax_ull(unsigned long long k) {
    #pragma unroll
    for (int o = 16; o; o >>= 1) {
        unsigned long long other = __shfl_xor_sync(0xffffffffu, k, o);
        if (other > k) k = other;
    }
    return k;
}

__global__ void perm_kernel(const float* __restrict__ ker) {
    int k = blockIdx.x * 8 + (threadIdx.x >> 5);
    int f = threadIdx.x & 31;
    const float* K = ker + (size_t)k * 1024;
    float s = 0.f, t = 0.f;
    #pragma unroll
    for (int x = 0; x < 32; x++) {
        float c = cospif((float)((2 * x + 1) * f) * (1.0f / 64.0f));
        s = fmaf(K[x],      c, s);
        t = fmaf(K[x * 32], c, t);
    }
    unsigned long long ks = (((unsigned long long)__float_as_uint(fabsf(s))) << 32) | (unsigned)f;
    unsigned long long kt = (((unsigned long long)__float_as_uint(fabsf(t))) << 32) | (unsigned)f;
    ks = lanemax_ull(ks);
    kt = lanemax_ull(kt);
    if (f == 0) {
        g_pos[(int)(kt & 31u) * 32 + (int)(ks & 31u)] = k;
    }
}

// ---------------- main fused kernel ----------------
// Grid: (ng=2, m=16, b=32). CTA = 768 threads, one 32-row x 256-col strip (8 blocks).
// tmp planes: [c][v][x] at c*8448 + v*264 + (x/32)*33 + (x%32); c = R,G,B DCT_v,
// then mixed in place to Y,Cb,Cr DCT_v (linearity).
static constexpr int PLANE_FLOATS = 32 * 264;          // 8448
static constexpr int TMP_FLOATS = 3 * PLANE_FLOATS;    // 25344 floats = 101376 B
static constexpr int PLANE_V4 = PLANE_FLOATS / 4;      // 2112

__global__ void __launch_bounds__(768, 1)
dct_main(const float* __restrict__ rgb, float* __restrict__ out) {
    extern __shared__ float tmp[];
    __shared__ int pos_s[1024];

    const int tid = threadIdx.x;
    const int ng = blockIdx.x;   // n-group (8 blocks each)
    const int m  = blockIdx.y;   // block row
    const int b  = blockIdx.z;   // batch

    if (tid < 1024) pos_s[tid] = g_pos[tid];
    if (tid < 256)  pos_s[768 + tid] = g_pos[768 + tid];

    // ---- stage 1: per-RGB-plane vertical butterfly DCT. thread = (c, col). ----
    {
        const int c = tid >> 8;          // 0..2 (R,G,B)
        const int col = tid & 255;
        const size_t plane = (size_t)512 * 512;
        const float* q = rgb + (size_t)b * 3 * plane + (size_t)c * plane
                             + (size_t)(m * 32) * 512 + ng * 256 + col;

        float acc[32];
        #pragma unroll
        for (int v = 0; v < 32; v++) acc[v] = 0.f;

        S1P<0>::run(q, acc);

        float* tb = tmp + c * PLANE_FLOATS + (col >> 5) * 33 + (col & 31);
        #pragma unroll
        for (int v = 0; v < 32; v++)
            tb[v * 264] = acc[v];
    }
    __syncthreads();

    // ---- mix pass: RGB DCT_v planes -> (2*Y, Cb', Cr') DCT_v in place ----
    // py = 2*y0 (the "-1" is constant -> only shifts the Y DC coeff; fixed below).
    {
        float4* t4 = reinterpret_cast<float4*>(tmp);
        #pragma unroll
        for (int k = 0; k < 3; k++) {
            int i = tid + k * 768;
            if (i < PLANE_V4) {
                float4 r4 = t4[i];
                float4 g4 = t4[PLANE_V4 + i];
                float4 b4 = t4[2 * PLANE_V4 + i];
                float4 yo, cbo, cro;
                {
                    float y0;
                    y0 = fmaf(0.299f, r4.x, fmaf(0.587f, g4.x, 0.114f * b4.x));
                    yo.x = 2.0f * y0; cbo.x = (b4.x - y0) * 1.128f; cro.x = (r4.x - y0) * 1.426f;
                    y0 = fmaf(0.299f, r4.y, fmaf(0.587f, g4.y, 0.114f * b4.y));
                    yo.y = 2.0f * y0; cbo.y = (b4.y - y0) * 1.128f; cro.y = (r4.y - y0) * 1.426f;
                    y0 = fmaf(0.299f, r4.z, fmaf(0.587f, g4.z, 0.114f * b4.z));
                    yo.z = 2.0f * y0; cbo.z = (b4.z - y0) * 1.128f; cro.z = (r4.z - y0) * 1.426f;
                    y0 = fmaf(0.299f, r4.w, fmaf(0.587f, g4.w, 0.114f * b4.w));
                    yo.w = 2.0f * y0; cbo.w = (b4.w - y0) * 1.128f; cro.w = (r4.w - y0) * 1.426f;
                }
                t4[i] = yo;
                t4[PLANE_V4 + i] = cbo;
                t4[2 * PLANE_V4 + i] = cro;
            }
        }
    }
    __syncthreads();

    // ---- stage 2: horizontal butterfly DCT. thread = (c, v, nblk). ----
    {
        const int c = tid >> 8;             // 0..2 (Y,Cb,Cr)
        const int v = (tid >> 3) & 31;
        const int nblk = tid & 7;
        const float* t = tmp + c * PLANE_FLOATS + v * 264 + nblk * 33;

        float a2[32];
        #pragma unroll
        for (int u = 0; u < 32; u++) a2[u] = 0.f;

        S2P<0>::run(t, a2);

        if ((tid >> 3) == 0) a2[0] -= 32.0f;   // c==0 && v==0: the "-1" offset's DC term

        const int n = ng * 8 + nblk;
        float* obc = out + (size_t)b * 3072 * 256 + (size_t)c * 1024 * 256 + m * 16 + n;
        const int* pv = pos_s + v * 32;
        #pragma unroll
        for (int u = 0; u < 32; u++) {
            obc[(size_t)pv[u] * 256] = a2[u];  // bijective: every output written once
        }
    }
}

// ---------------- launch ----------------
extern "C" void kernel_launch(void* const* d_in, const int* in_sizes, int n_in,
                              void* d_out, int out_size) {
    const float* rgb = (const float*)d_in[0];
    const float* ker = (const float*)d_in[1];
    float* out = (float*)d_out;

    perm_kernel<<<128, 256>>>(ker);

    cudaFuncSetAttribute(dct_main, cudaFuncAttributeMaxDynamicSharedMemorySize,
                         TMP_FLOATS * (int)sizeof(float));
    dct_main<<<dim3(2, 16, 32), 768, TMP_FLOATS * (int)sizeof(float)>>>(rgb, out);
}